// round 1
// baseline (speedup 1.0000x reference)
#include <cuda_runtime.h>

// Problem constants (fixed shapes from reference setup_inputs)
#define B 64
#define N 10000
#define D 128
#define F 4
#define CHUNKS 16
#define ROWS_PER_CHUNK ((N + CHUNKS - 1) / CHUNKS)   // 625
#define LN_EPS 0.001f

// Deterministic partial-sum scratch: [B][CHUNKS][D] floats = 512 KB
__device__ float g_partials[B * CHUNKS * D];

// ---------------------------------------------------------------------------
// Kernel 1: streaming sum of H over N, per (b, chunk). Fully coalesced float4.
// Block: 256 threads = 8 row-groups x 32 lanes (each lane covers 4 of 128 d's).
// ---------------------------------------------------------------------------
__global__ __launch_bounds__(256) void sum_h_kernel(const float* __restrict__ H) {
    const int chunk = blockIdx.x;
    const int b     = blockIdx.y;
    const int tid   = threadIdx.x;
    const int lane  = tid & 31;   // which float4 of the row (32 float4 = 128 floats)
    const int grp   = tid >> 5;   // 8 row groups

    const int r0 = chunk * ROWS_PER_CHUNK;
    int r1 = r0 + ROWS_PER_CHUNK;
    if (r1 > N) r1 = N;

    const float4* __restrict__ Hv = (const float4*)H;
    const int row_v = D / 4;  // 32

    float4 acc = make_float4(0.f, 0.f, 0.f, 0.f);
    for (int r = r0 + grp; r < r1; r += 8) {
        float4 v = Hv[(b * N + r) * row_v + lane];
        acc.x += v.x; acc.y += v.y; acc.z += v.z; acc.w += v.w;
    }

    __shared__ float4 sm[256];
    sm[tid] = acc;
    __syncthreads();

    if (tid < 32) {
        float4 s = sm[lane];
        #pragma unroll
        for (int g = 1; g < 8; g++) {
            float4 v = sm[g * 32 + lane];
            s.x += v.x; s.y += v.y; s.z += v.z; s.w += v.w;
        }
        ((float4*)g_partials)[(b * CHUNKS + chunk) * row_v + lane] = s;
    }
}

// ---------------------------------------------------------------------------
// Kernel 2: per-batch fuse: reduce partials -> mean, gather+relu, GEMM(640->128),
// relu, layernorm. 64 blocks x 128 threads (thread d = output column).
// ---------------------------------------------------------------------------
__global__ __launch_bounds__(128) void fuse_kernel(
    const float* __restrict__ H,
    const int*   __restrict__ indice,
    const float* __restrict__ W,      // [(F+1)*D, D] row-major
    const float* __restrict__ bias,   // [D]
    const float* __restrict__ gamma,  // [D]
    const float* __restrict__ beta,   // [D]
    float*       __restrict__ out)    // [B, 1, D]
{
    const int b = blockIdx.x;
    const int d = threadIdx.x;  // 0..127

    __shared__ float emb[(F + 1) * D];   // 640 floats
    __shared__ float red[4];

    // graph_emb = mean over N (reduce the 16 chunk partials, fixed order)
    float s = 0.f;
    #pragma unroll
    for (int c = 0; c < CHUNKS; c++)
        s += g_partials[(b * CHUNKS + c) * D + d];
    emb[F * D + d] = s * (1.0f / (float)N);

    // gathered rows, relu
    #pragma unroll
    for (int f = 0; f < F; f++) {
        int idx = indice[b * F + f];
        float v = H[((long long)b * N + idx) * D + d];
        emb[f * D + d] = fmaxf(v, 0.0f);
    }
    __syncthreads();

    // x_d = relu( emb . W[:, d] + bias[d] )
    float x = bias[d];
    #pragma unroll 16
    for (int i = 0; i < (F + 1) * D; i++)
        x = fmaf(emb[i], W[i * D + d], x);
    x = fmaxf(x, 0.0f);

    // ---- layernorm over the 128 threads ----
    const int lane = d & 31, wid = d >> 5;

    // mean
    float v = x;
    #pragma unroll
    for (int o = 16; o > 0; o >>= 1) v += __shfl_xor_sync(0xffffffffu, v, o);
    if (lane == 0) red[wid] = v;
    __syncthreads();
    float mu = (red[0] + red[1] + red[2] + red[3]) * (1.0f / (float)D);
    __syncthreads();

    // variance
    float dx = x - mu;
    float v2 = dx * dx;
    #pragma unroll
    for (int o = 16; o > 0; o >>= 1) v2 += __shfl_xor_sync(0xffffffffu, v2, o);
    if (lane == 0) red[wid] = v2;
    __syncthreads();
    float var = (red[0] + red[1] + red[2] + red[3]) * (1.0f / (float)D);

    out[b * D + d] = dx * rsqrtf(var + LN_EPS) * gamma[d] + beta[d];
}

// ---------------------------------------------------------------------------
extern "C" void kernel_launch(void* const* d_in, const int* in_sizes, int n_in,
                              void* d_out, int out_size) {
    const float* H      = (const float*)d_in[0];
    const int*   indice = (const int*)  d_in[1];
    const float* W      = (const float*)d_in[2];
    const float* bias   = (const float*)d_in[3];
    const float* gamma  = (const float*)d_in[4];
    const float* beta   = (const float*)d_in[5];
    float* out = (float*)d_out;

    dim3 grid1(CHUNKS, B);
    sum_h_kernel<<<grid1, 256>>>(H);
    fuse_kernel<<<B, 128>>>(H, indice, W, bias, gamma, beta, out);
}

// round 2
// speedup vs baseline: 1.2513x; 1.2513x over previous
#include <cuda_runtime.h>

// Problem constants (fixed shapes from reference setup_inputs)
#define B 64
#define N 10000
#define D 128
#define F 4
#define CHUNKS 16
#define ROWS_PER_CHUNK ((N + CHUNKS - 1) / CHUNKS)   // 625
#define LN_EPS 0.001f
#define EMB_LEN ((F + 1) * D)                        // 640

// Deterministic partial-sum scratch: [B][CHUNKS][D] floats = 512 KB
__device__ float g_partials[B * CHUNKS * D];

// ---------------------------------------------------------------------------
// Kernel 1: streaming sum of H over N, per (b, chunk). Fully coalesced float4,
// streaming loads (H is 328MB — keep it out of L2), unroll x4 for MLP.
// Block: 256 threads = 8 row-groups x 32 lanes (lane = float4 within 128-d row).
// ---------------------------------------------------------------------------
__global__ __launch_bounds__(256) void sum_h_kernel(const float* __restrict__ H) {
    const int chunk = blockIdx.x;
    const int b     = blockIdx.y;
    const int tid   = threadIdx.x;
    const int lane  = tid & 31;
    const int grp   = tid >> 5;   // 8 row groups

    const int r0 = chunk * ROWS_PER_CHUNK;
    int r1 = r0 + ROWS_PER_CHUNK;
    if (r1 > N) r1 = N;

    const float4* __restrict__ Hv = (const float4*)H;
    const int row_v = D / 4;  // 32

    float4 a0 = make_float4(0.f,0.f,0.f,0.f);
    float4 a1 = make_float4(0.f,0.f,0.f,0.f);
    float4 a2 = make_float4(0.f,0.f,0.f,0.f);
    float4 a3 = make_float4(0.f,0.f,0.f,0.f);

    int r = r0 + grp;
    // main unrolled-by-4 loop: 4 independent in-flight loads per thread
    for (; r + 24 < r1; r += 32) {
        float4 v0 = __ldcs(&Hv[((long long)b * N + r     ) * row_v + lane]);
        float4 v1 = __ldcs(&Hv[((long long)b * N + r +  8) * row_v + lane]);
        float4 v2 = __ldcs(&Hv[((long long)b * N + r + 16) * row_v + lane]);
        float4 v3 = __ldcs(&Hv[((long long)b * N + r + 24) * row_v + lane]);
        a0.x += v0.x; a0.y += v0.y; a0.z += v0.z; a0.w += v0.w;
        a1.x += v1.x; a1.y += v1.y; a1.z += v1.z; a1.w += v1.w;
        a2.x += v2.x; a2.y += v2.y; a2.z += v2.z; a2.w += v2.w;
        a3.x += v3.x; a3.y += v3.y; a3.z += v3.z; a3.w += v3.w;
    }
    for (; r < r1; r += 8) {
        float4 v0 = __ldcs(&Hv[((long long)b * N + r) * row_v + lane]);
        a0.x += v0.x; a0.y += v0.y; a0.z += v0.z; a0.w += v0.w;
    }
    a0.x += a1.x + a2.x + a3.x;
    a0.y += a1.y + a2.y + a3.y;
    a0.z += a1.z + a2.z + a3.z;
    a0.w += a1.w + a2.w + a3.w;

    __shared__ float4 sm[256];
    sm[tid] = a0;
    __syncthreads();

    if (tid < 32) {
        float4 s = sm[lane];
        #pragma unroll
        for (int g = 1; g < 8; g++) {
            float4 v = sm[g * 32 + lane];
            s.x += v.x; s.y += v.y; s.z += v.z; s.w += v.w;
        }
        ((float4*)g_partials)[(b * CHUNKS + chunk) * row_v + lane] = s;
    }
}

// ---------------------------------------------------------------------------
// Kernel 2: per-batch fuse. 64 blocks x 640 threads.
// Thread (seg, d): seg = tid/128 in [0,5), d = tid%128.
// Each thread computes a 128-term partial dot of emb[seg*128 : seg*128+128]
// with W[:, d]; 5-way smem reduce; first 128 threads do relu + layernorm.
// ---------------------------------------------------------------------------
__global__ __launch_bounds__(EMB_LEN) void fuse_kernel(
    const float* __restrict__ H,
    const int*   __restrict__ indice,
    const float* __restrict__ W,      // [640, 128] row-major
    const float* __restrict__ bias,   // [128]
    const float* __restrict__ gamma,  // [128]
    const float* __restrict__ beta,   // [128]
    float*       __restrict__ out)    // [B, 1, 128]
{
    const int b   = blockIdx.x;
    const int tid = threadIdx.x;      // 0..639
    const int seg = tid >> 7;         // 0..4
    const int d   = tid & 127;        // 0..127

    __shared__ float emb[EMB_LEN];            // 640
    __shared__ float part[EMB_LEN];           // 640 (5 segments x 128)
    __shared__ float red[4];

    // ---- stage emb: segs 0..3 = gathered rows (relu), seg 4 = mean row ----
    if (seg < F) {
        const int idx = indice[b * F + seg];
        emb[tid] = fmaxf(H[((long long)b * N + idx) * D + d], 0.0f);
    } else {
        float s = 0.f;
        #pragma unroll
        for (int c = 0; c < CHUNKS; c++)
            s += g_partials[(b * CHUNKS + c) * D + d];
        emb[tid] = s * (1.0f / (float)N);
    }
    __syncthreads();

    // ---- partial dot: 128 terms, 4 accumulators ----
    const float* __restrict__ Wp = W + (seg * 128) * D + d;  // rows seg*128..+127, col d
    const float* __restrict__ ep = emb + seg * 128;

    float acc0 = 0.f, acc1 = 0.f, acc2 = 0.f, acc3 = 0.f;
    #pragma unroll
    for (int j = 0; j < 128; j += 4) {
        acc0 = fmaf(ep[j    ], Wp[(j    ) * D], acc0);
        acc1 = fmaf(ep[j + 1], Wp[(j + 1) * D], acc1);
        acc2 = fmaf(ep[j + 2], Wp[(j + 2) * D], acc2);
        acc3 = fmaf(ep[j + 3], Wp[(j + 3) * D], acc3);
    }
    part[tid] = (acc0 + acc1) + (acc2 + acc3);
    __syncthreads();

    // ---- first 128 threads: combine segments, relu, layernorm ----
    float x = 0.f;
    if (tid < D) {
        x = bias[d] + part[d] + part[D + d] + part[2 * D + d]
                    + part[3 * D + d] + part[4 * D + d];
        x = fmaxf(x, 0.0f);

        const int lane = d & 31, wid = d >> 5;

        // mean
        float v = x;
        #pragma unroll
        for (int o = 16; o > 0; o >>= 1) v += __shfl_xor_sync(0xffffffffu, v, o);
        if (lane == 0) red[wid] = v;
    }
    __syncthreads();
    if (tid < D) {
        const int lane = d & 31, wid = d >> 5;
        float mu = (red[0] + red[1] + red[2] + red[3]) * (1.0f / (float)D);

        float dx = x - mu;
        float v2 = dx * dx;
        #pragma unroll
        for (int o = 16; o > 0; o >>= 1) v2 += __shfl_xor_sync(0xffffffffu, v2, o);
        if (lane == 0) red[wid] = v2;
        __syncwarp();
        // need all 4 warps' v2 in red[]: cross-warp visibility via syncthreads below
    }
    __syncthreads();
    if (tid < D) {
        float mu = 0.f;  // recompute deterministic mean is not possible here; red now holds var parts
        // NOTE: red[] was overwritten with variance partials; recompute mu from x via shuffle again
        // to keep code simple and correct, redo mean using part[] storage:
        // (part still holds segment dots; reuse a dedicated path instead)
        // -- replaced below --
        (void)mu;
    }
    // ---- corrected layernorm epilogue (separate buffers, no reuse hazard) ----
    __shared__ float red_mu[4], red_var[4];
    if (tid < D) {
        const int lane = d & 31, wid = d >> 5;
        float v = x;
        #pragma unroll
        for (int o = 16; o > 0; o >>= 1) v += __shfl_xor_sync(0xffffffffu, v, o);
        if (lane == 0) red_mu[wid] = v;
    }
    __syncthreads();
    if (tid < D) {
        const int lane = d & 31, wid = d >> 5;
        float mu = (red_mu[0] + red_mu[1] + red_mu[2] + red_mu[3]) * (1.0f / (float)D);
        float dx = x - mu;
        float v2 = dx * dx;
        #pragma unroll
        for (int o = 16; o > 0; o >>= 1) v2 += __shfl_xor_sync(0xffffffffu, v2, o);
        if (lane == 0) red_var[wid] = v2;
    }
    __syncthreads();
    if (tid < D) {
        float mu  = (red_mu[0]  + red_mu[1]  + red_mu[2]  + red_mu[3])  * (1.0f / (float)D);
        float var = (red_var[0] + red_var[1] + red_var[2] + red_var[3]) * (1.0f / (float)D);
        out[b * D + d] = (x - mu) * rsqrtf(var + LN_EPS) * gamma[d] + beta[d];
    }
}

// ---------------------------------------------------------------------------
extern "C" void kernel_launch(void* const* d_in, const int* in_sizes, int n_in,
                              void* d_out, int out_size) {
    const float* H      = (const float*)d_in[0];
    const int*   indice = (const int*)  d_in[1];
    const float* W      = (const float*)d_in[2];
    const float* bias   = (const float*)d_in[3];
    const float* gamma  = (const float*)d_in[4];
    const float* beta   = (const float*)d_in[5];
    float* out = (float*)d_out;

    dim3 grid1(CHUNKS, B);
    sum_h_kernel<<<grid1, 256>>>(H);
    fuse_kernel<<<B, EMB_LEN>>>(H, indice, W, bias, gamma, beta, out);
}

// round 3
// speedup vs baseline: 1.2643x; 1.0104x over previous
#include <cuda_runtime.h>

// Problem constants (fixed shapes from reference setup_inputs)
#define B 64
#define N 10000
#define D 128
#define F 4
#define CHUNKS 37                                    // 64*37 = 2368 CTAs = 16.0 exact waves on 148 SMs
#define ROWS_PER_CHUNK ((N + CHUNKS - 1) / CHUNKS)   // 271
#define LN_EPS 0.001f
#define EMB_LEN ((F + 1) * D)                        // 640
#define NWARP 20                                     // 640 threads

// Deterministic partial-sum scratch: [B][CHUNKS][D] floats
__device__ float g_partials[B * CHUNKS * D];

// ---------------------------------------------------------------------------
// Kernel 1: streaming sum of H over N, per (b, chunk). Coalesced float4,
// streaming loads, unroll x4 for MLP. 256 thr = 8 row-groups x 32 lanes.
// ---------------------------------------------------------------------------
__global__ __launch_bounds__(256) void sum_h_kernel(const float* __restrict__ H) {
    const int chunk = blockIdx.x;
    const int b     = blockIdx.y;
    const int tid   = threadIdx.x;
    const int lane  = tid & 31;
    const int grp   = tid >> 5;   // 8 row groups

    const int r0 = chunk * ROWS_PER_CHUNK;
    int r1 = r0 + ROWS_PER_CHUNK;
    if (r1 > N) r1 = N;

    const float4* __restrict__ Hv = (const float4*)H;
    const int row_v = D / 4;  // 32

    float4 a0 = make_float4(0.f,0.f,0.f,0.f);
    float4 a1 = make_float4(0.f,0.f,0.f,0.f);
    float4 a2 = make_float4(0.f,0.f,0.f,0.f);
    float4 a3 = make_float4(0.f,0.f,0.f,0.f);

    int r = r0 + grp;
    for (; r + 24 < r1; r += 32) {
        float4 v0 = __ldcs(&Hv[((long long)b * N + r     ) * row_v + lane]);
        float4 v1 = __ldcs(&Hv[((long long)b * N + r +  8) * row_v + lane]);
        float4 v2 = __ldcs(&Hv[((long long)b * N + r + 16) * row_v + lane]);
        float4 v3 = __ldcs(&Hv[((long long)b * N + r + 24) * row_v + lane]);
        a0.x += v0.x; a0.y += v0.y; a0.z += v0.z; a0.w += v0.w;
        a1.x += v1.x; a1.y += v1.y; a1.z += v1.z; a1.w += v1.w;
        a2.x += v2.x; a2.y += v2.y; a2.z += v2.z; a2.w += v2.w;
        a3.x += v3.x; a3.y += v3.y; a3.z += v3.z; a3.w += v3.w;
    }
    for (; r < r1; r += 8) {
        float4 v0 = __ldcs(&Hv[((long long)b * N + r) * row_v + lane]);
        a0.x += v0.x; a0.y += v0.y; a0.z += v0.z; a0.w += v0.w;
    }
    a0.x += a1.x + a2.x + a3.x;
    a0.y += a1.y + a2.y + a3.y;
    a0.z += a1.z + a2.z + a3.z;
    a0.w += a1.w + a2.w + a3.w;

    __shared__ float4 sm[256];
    sm[tid] = a0;
    __syncthreads();

    if (tid < 32) {
        float4 s = sm[lane];
        #pragma unroll
        for (int g = 1; g < 8; g++) {
            float4 v = sm[g * 32 + lane];
            s.x += v.x; s.y += v.y; s.z += v.z; s.w += v.w;
        }
        ((float4*)g_partials)[(b * CHUNKS + chunk) * row_v + lane] = s;
    }
}

// ---------------------------------------------------------------------------
// Kernel 2: per-batch fuse. 64 blocks x 640 threads (20 warps).
// Warp w owns W rows [32w, 32w+32); lane l owns output cols [4l, 4l+4) via
// float4 loads of W. emb broadcast from smem. 20-way combine, relu, layernorm.
// ---------------------------------------------------------------------------
__global__ __launch_bounds__(EMB_LEN) void fuse_kernel(
    const float* __restrict__ H,
    const int*   __restrict__ indice,
    const float* __restrict__ W,      // [640, 128] row-major
    const float* __restrict__ bias,   // [128]
    const float* __restrict__ gamma,  // [128]
    const float* __restrict__ beta,   // [128]
    float*       __restrict__ out)    // [B, 1, 128]
{
    const int b    = blockIdx.x;
    const int tid  = threadIdx.x;     // 0..639
    const int lane = tid & 31;        // col group: cols 4*lane .. 4*lane+3
    const int w    = tid >> 5;        // warp 0..19: rows 32w..32w+31
    const int seg  = tid >> 7;        // 0..4 (for emb staging)
    const int d    = tid & 127;

    __shared__ float emb[EMB_LEN];              // 640
    __shared__ float part[NWARP * D];           // 20 x 128 = 10 KB
    __shared__ float red_mu[4], red_var[4];

    // ---- stage emb: segs 0..3 = gathered rows (relu), seg 4 = mean row ----
    if (seg < F) {
        const int idx = __ldg(&indice[b * F + seg]);
        emb[tid] = fmaxf(__ldg(&H[((long long)b * N + idx) * D + d]), 0.0f);
    } else {
        float s = 0.f;
        for (int c = 0; c < CHUNKS; c++)
            s += g_partials[(b * CHUNKS + c) * D + d];
        emb[tid] = s * (1.0f / (float)N);
    }
    __syncthreads();

    // ---- partial GEMM: 32 rows per warp, float4 over 4 columns ----
    const float4* __restrict__ W4 = (const float4*)W;   // [640][32] float4
    const int rbase = w * 32;

    float4 acc0 = make_float4(0.f,0.f,0.f,0.f);
    float4 acc1 = make_float4(0.f,0.f,0.f,0.f);
    #pragma unroll
    for (int j = 0; j < 32; j += 2) {
        float  e0 = emb[rbase + j];
        float  e1 = emb[rbase + j + 1];
        float4 w0 = __ldg(&W4[(rbase + j    ) * 32 + lane]);
        float4 w1 = __ldg(&W4[(rbase + j + 1) * 32 + lane]);
        acc0.x = fmaf(e0, w0.x, acc0.x); acc0.y = fmaf(e0, w0.y, acc0.y);
        acc0.z = fmaf(e0, w0.z, acc0.z); acc0.w = fmaf(e0, w0.w, acc0.w);
        acc1.x = fmaf(e1, w1.x, acc1.x); acc1.y = fmaf(e1, w1.y, acc1.y);
        acc1.z = fmaf(e1, w1.z, acc1.z); acc1.w = fmaf(e1, w1.w, acc1.w);
    }
    acc0.x += acc1.x; acc0.y += acc1.y; acc0.z += acc1.z; acc0.w += acc1.w;
    ((float4*)part)[w * 32 + lane] = acc0;
    __syncthreads();

    // ---- first 128 threads: combine 20 partials, relu, layernorm ----
    float x = 0.f;
    if (tid < D) {
        x = bias[d];
        #pragma unroll
        for (int k = 0; k < NWARP; k++)
            x += part[k * D + d];
        x = fmaxf(x, 0.0f);

        float v = x;
        #pragma unroll
        for (int o = 16; o > 0; o >>= 1) v += __shfl_xor_sync(0xffffffffu, v, o);
        if (lane == 0) red_mu[tid >> 5] = v;
    }
    __syncthreads();
    if (tid < D) {
        float mu = (red_mu[0] + red_mu[1] + red_mu[2] + red_mu[3]) * (1.0f / (float)D);
        float dx = x - mu;
        float v2 = dx * dx;
        #pragma unroll
        for (int o = 16; o > 0; o >>= 1) v2 += __shfl_xor_sync(0xffffffffu, v2, o);
        if (lane == 0) red_var[tid >> 5] = v2;
    }
    __syncthreads();
    if (tid < D) {
        float mu  = (red_mu[0]  + red_mu[1]  + red_mu[2]  + red_mu[3])  * (1.0f / (float)D);
        float var = (red_var[0] + red_var[1] + red_var[2] + red_var[3]) * (1.0f / (float)D);
        out[b * D + d] = (x - mu) * rsqrtf(var + LN_EPS) * gamma[d] + beta[d];
    }
}

// ---------------------------------------------------------------------------
extern "C" void kernel_launch(void* const* d_in, const int* in_sizes, int n_in,
                              void* d_out, int out_size) {
    const float* H      = (const float*)d_in[0];
    const int*   indice = (const int*)  d_in[1];
    const float* W      = (const float*)d_in[2];
    const float* bias   = (const float*)d_in[3];
    const float* gamma  = (const float*)d_in[4];
    const float* beta   = (const float*)d_in[5];
    float* out = (float*)d_out;

    dim3 grid1(CHUNKS, B);
    sum_h_kernel<<<grid1, 256>>>(H);
    fuse_kernel<<<B, EMB_LEN>>>(H, indice, W, bias, gamma, beta, out);
}